// round 9
// baseline (speedup 1.0000x reference)
#include <cuda_runtime.h>
#include <math.h>

#define B      128
#define P      8732
#define C      21
#define NOBJ   20
#define WT     512
#define NTILES 18                 // ceil(P/WT)
#define NLSE   (NTILES*B)         // 2304
#define S4     4
#define QTR    (P/S4)             // 2183
#define NMATCH (B*S4)             // 512
#define NWORK  (NLSE+NMATCH)      // 2816 = 256*11
#define TC     5                  // truth chunk size
#define NC     (NOBJ/TC)          // 4 chunks
#define NSLOT  ((QTR+WT-1)/WT)    // 5

typedef unsigned long long ull;

__device__ ull           g_bp[B*NOBJ];
__device__ unsigned char g_code[B*P];      // bestn | pos<<7
__device__ float         g_mine[B*P];      // neg: loss_c ; pos: -(ce+2)
__device__ float         g_lse[B*P];
__device__ float         g_ll[B];
__device__ int           g_np[B];
__device__ float         g_lc[B];
__device__ float         g_ce0;
__device__ unsigned      g_ticket;

__device__ __forceinline__ float sl1(float x) {
    float a = fabsf(x);
    return a < 1.0f ? 0.5f * a * a : a - 0.5f;
}

// ------------- kernel 0: init -------------------------------------------------
__global__ void k_init() {
    int i = blockIdx.x * 1024 + threadIdx.x;
    if (i < B*NOBJ) g_bp[i] = 0xFFFFFFFFull;   // key(iou=0, p=0)
    if (i == 0)     g_ticket = 0u;
}

// ------------- kernel 1: fused match (compute) + lse (DRAM) roles -------------
__global__ __launch_bounds__(WT) void k_work(const float*  __restrict__ conf,
                                             const float4* __restrict__ priors,
                                             const float*  __restrict__ targets)
{
    extern __shared__ float dsm[];
    int bx = blockIdx.x, tid = threadIdx.x;
    int grp = bx / 11, rem = bx % 11;

    if (rem < 2) {
        // =============== match role: 512 blocks, 4 per image ==================
        ull*    s_bp   = (ull*)dsm;            // 20 ull  [0,160)B
        float4* s_tr4  = (float4*)(dsm + 40);  // 20 f4   [160,480)B
        float*  s_area = dsm + 120;            // 20 f    [480,560)B

        int midx = grp*2 + rem;                // 0..511
        int b = midx >> 2, quarter = midx & 3;
        int p0 = quarter * QTR;
        const float* tg = targets + b*NOBJ*5;
        if (tid < NOBJ) {
            float a0 = tg[tid*5+0], a1 = tg[tid*5+1];
            float a2 = tg[tid*5+2], a3 = tg[tid*5+3];
            s_tr4[tid]  = make_float4(a0, a1, a2, a3);
            s_area[tid] = (a2 - a0) * (a3 - a1);
            s_bp[tid]   = 0ull;
        }
        __syncthreads();

        float bestv[NSLOT]; int bestn[NSLOT];
        #pragma unroll
        for (int j = 0; j < NSLOT; j++) { bestv[j] = -1.0f; bestn[j] = 0; }
        int lane = tid & 31;

        for (int c = 0; c < NC; c++) {         // truth chunks of 5 -> low regs
            ull bpl[TC];
            #pragma unroll
            for (int n = 0; n < TC; n++) bpl[n] = 0ull;
            #pragma unroll
            for (int j = 0; j < NSLOT; j++) {
                int i = tid + j*WT;
                if (i < QTR) {
                    int p = p0 + i;
                    float4 pr = __ldg(priors + p);      // L1-hit after chunk 0
                    float hw = pr.z*0.5f, hh = pr.w*0.5f;
                    float bx0 = pr.x-hw, by0 = pr.y-hh;
                    float bx1 = pr.x+hw, by1 = pr.y+hh;
                    float area_b = (bx1-bx0)*(by1-by0);
                    unsigned pinv = 0xFFFFFFFFu - (unsigned)p;
                    #pragma unroll
                    for (int n5 = 0; n5 < TC; n5++) {
                        int n = c*TC + n5;
                        float4 t = s_tr4[n]; float ar = s_area[n];
                        float w = fmaxf(fminf(t.z, bx1) - fmaxf(t.x, bx0), 0.0f);
                        float h = fmaxf(fminf(t.w, by1) - fmaxf(t.y, by0), 0.0f);
                        float inter = w * h;
                        float iou = inter / ((ar + area_b) - inter);
                        if (iou > bestv[j]) { bestv[j] = iou; bestn[j] = n; }
                        ull key = ((ull)__float_as_uint(iou) << 32) | (ull)pinv;
                        if (key > bpl[n5]) bpl[n5] = key;
                    }
                }
            }
            #pragma unroll
            for (int n5 = 0; n5 < TC; n5++) {
                ull k = bpl[n5];
                #pragma unroll
                for (int o = 16; o > 0; o >>= 1) {
                    ull x = __shfl_down_sync(0xffffffffu, k, o);
                    if (x > k) k = x;
                }
                if (lane == 0) atomicMax(&s_bp[c*TC + n5], k);
            }
        }
        #pragma unroll
        for (int j = 0; j < NSLOT; j++) {
            int i = tid + j*WT;
            if (i < QTR)
                g_code[b*P + p0 + i] =
                    (unsigned char)(bestn[j] | ((bestv[j] < 0.5f) ? 0 : 0x80));
        }
        __syncthreads();
        if (tid < NOBJ) atomicMax(&g_bp[b*NOBJ + tid], s_bp[tid]);
    } else {
        // =============== lse role: 2304 blocks, pure streaming ================
        float* s_stage = dsm;                  // WT*C floats = 43008 B
        int lidx = grp*9 + (rem - 2);
        int b = lidx / NTILES, tile = lidx % NTILES;
        int t0 = tile * WT, rows = min(WT, P - t0);
        const float* src = conf + ((size_t)b*P + t0) * C;
        int elems = rows * C;
        for (int i = tid; i < elems; i += WT) s_stage[i] = __ldg(src + i);
        __syncthreads();
        if (tid < rows) {
            const float* r = s_stage + tid * C;     // stride 21: conflict-free
            float mx = r[0];
            #pragma unroll
            for (int c2 = 1; c2 < C; c2++) mx = fmaxf(mx, r[c2]);
            float s = 0.0f;
            #pragma unroll
            for (int c2 = 0; c2 < C; c2++) s += __expf(r[c2] - mx);
            float lse = mx + __logf(s);
            size_t idx = (size_t)b*P + t0 + tid;
            g_lse[idx]  = lse;
            g_mine[idx] = lse - r[0];               // negative assumption
        }
    }
}

// ------------- kernel 2: positive fixup + loc loss + numpos -------------------
__global__ __launch_bounds__(1024) void k_fix(const float*  __restrict__ conf,
                                              const float4* __restrict__ priors,
                                              const float*  __restrict__ loc,
                                              const float*  __restrict__ targets)
{
    __shared__ unsigned char s_code[P];
    __shared__ float s_tr[NOBJ*5];
    __shared__ int   s_p2[NOBJ];
    __shared__ float s_red[1024];
    __shared__ int   s_redi[1024];

    int b = blockIdx.x, tid = threadIdx.x;
    const unsigned* gc = (const unsigned*)(g_code + b*P);  // P % 4 == 0
    unsigned* sc = (unsigned*)s_code;
    for (int i = tid; i < P/4; i += 1024) sc[i] = gc[i];
    if (tid < NOBJ*5) s_tr[tid] = targets[b*NOBJ*5 + tid];
    if (tid < NOBJ)
        s_p2[tid] = (int)(0xFFFFFFFFu - (unsigned)(g_bp[b*NOBJ + tid] & 0xFFFFFFFFull));
    __syncthreads();
    if (tid == 0) {   // ascending m, last write wins = JAX "chosen = max n"
        for (int m = 0; m < NOBJ; m++) s_code[s_p2[m]] = (unsigned char)(m | 0x80);
    }
    __syncthreads();

    float ll = 0.0f; int np = 0;
    for (int p = tid; p < P; p += 1024) {
        unsigned char code = s_code[p];
        size_t idx = (size_t)b*P + p;
        if (code & 0x80) {
            int n = code & 31;
            np++;
            int cf = (int)s_tr[n*5+4] + 1;
            float lse = g_lse[idx];
            float rcf = __ldg(conf + idx*C + cf);
            g_mine[idx] = -((lse - rcf) + 2.0f);       // encode positive CE
            float4 pr = __ldg(priors + p);
            float a0 = s_tr[n*5+0], a1 = s_tr[n*5+1];
            float a2 = s_tr[n*5+2], a3 = s_tr[n*5+3];
            float gx = ((a0 + a2) * 0.5f - pr.x) / (0.1f * pr.z);
            float gy = ((a1 + a3) * 0.5f - pr.y) / (0.1f * pr.w);
            float gw = logf((a2 - a0) / pr.z) * 5.0f;
            float gh = logf((a3 - a1) / pr.w) * 5.0f;
            float4 ld = __ldg(((const float4*)loc) + idx);
            ll += sl1(ld.x - gx) + sl1(ld.y - gy) + sl1(ld.z - gw) + sl1(ld.w - gh);
        } else if (b == 0 && p == 0) {
            // clamped[0]=1 quirk: recompute lse with IDENTICAL op sequence
            float rr[C];
            #pragma unroll
            for (int c2 = 0; c2 < C; c2++) rr[c2] = __ldg(conf + c2);
            float mx = rr[0];
            #pragma unroll
            for (int c2 = 1; c2 < C; c2++) mx = fmaxf(mx, rr[c2]);
            float s = 0.0f;
            #pragma unroll
            for (int c2 = 0; c2 < C; c2++) s += __expf(rr[c2] - mx);
            float lse = mx + __logf(s);
            g_ce0      = lse - rr[0];                  // true CE if selected
            g_mine[0]  = lse - rr[1];                  // mining value uses class 1
        }
    }
    s_red[tid] = ll; s_redi[tid] = np; __syncthreads();
    for (int o = 512; o > 0; o >>= 1) {
        if (tid < o) { s_red[tid] += s_red[tid + o]; s_redi[tid] += s_redi[tid + o]; }
        __syncthreads();
    }
    if (tid == 0) { g_ll[b] = s_red[0]; g_np[b] = s_redi[0]; }
}

// ------------- kernel 3: hard-negative mining + final reduce ------------------
__global__ __launch_bounds__(1024) void k_mine(float* __restrict__ out)
{
    __shared__ float    s_v[P];
    __shared__ int      hist[256];
    __shared__ int      cnts[1024 + 32];
    __shared__ float    s_red[1024];
    __shared__ unsigned s_pref;
    __shared__ int      s_kleft;
    __shared__ bool     s_last;

    int b = blockIdx.x, tid = threadIdx.x;
    int lane = tid & 31, wid = tid >> 5;
    int* s_ws = cnts + 1024;

    float ce_pos = 0.0f;
    for (int p = tid; p < P; p += 1024) {
        float v = g_mine[(size_t)b*P + p];
        s_v[p] = v;
        if (v < 0.0f) ce_pos += -v - 2.0f;             // decode positive CE
    }
    __syncthreads();

    int np = g_np[b];
    int k = 3 * np; if (k > P - 1) k = P - 1;
    int negc = P - np;
    const int CH = (P + 1023) / 1024;                   // 9
    int lo = tid * CH, hi = min(lo + CH, P);
    float nsum = 0.0f;

    if (k >= negc) {
        for (int i = lo; i < hi; i++) { float v = s_v[i]; if (v >= 0.0f) nsum += v; }
        if (b == 0 && tid == 0) { float v0 = s_v[0]; if (v0 >= 0.0f) nsum += g_ce0 - v0; }
    } else {
        unsigned pref = 0; int kleft = k;
        for (int shift = 24; shift >= 0; shift -= 8) {
            if (tid < 256) hist[tid] = 0;
            __syncthreads();
            #pragma unroll
            for (int j = 0; j < CH; j++) {              // warp-aggregated atomics
                int i = lo + j;
                bool act = (i < P);
                float v = act ? s_v[i] : -1.0f;
                unsigned key = (v < 0.0f) ? 0u : __float_as_uint(v);
                unsigned kh = key >> shift;
                bool ok = act && (v >= 0.0f) &&
                          ((shift == 24) || ((kh >> 8) == pref));
                unsigned bin = ok ? (kh & 255u) : (256u + (unsigned)lane);
                unsigned m = __match_any_sync(0xffffffffu, bin);
                if (ok && lane == (__ffs(m) - 1))
                    atomicAdd(&hist[bin], __popc(m));
            }
            __syncthreads();
            if (wid == 0) {                              // warp-only bin select
                int c[8]; int tot = 0;
                #pragma unroll
                for (int j = 0; j < 8; j++) { c[j] = hist[lane*8 + j]; tot += c[j]; }
                int suf = tot;
                #pragma unroll
                for (int o = 1; o < 32; o <<= 1) {
                    int y = __shfl_down_sync(0xffffffffu, suf, o);
                    if (lane + o < 32) suf += y;
                }
                int cum = suf - tot;                     // counts strictly above lane
                #pragma unroll
                for (int j = 7; j >= 0; j--) {
                    if (cum < kleft && cum + c[j] >= kleft) {
                        s_pref  = (pref << 8) | (unsigned)(lane*8 + j);
                        s_kleft = kleft - cum;
                    }
                    cum += c[j];
                }
            }
            __syncthreads();
            pref = s_pref; kleft = s_kleft;
        }
        unsigned T = pref; int quota = kleft;            // quota >= 1

        int ct = 0;
        for (int i = lo; i < hi; i++) {
            float v = s_v[i];
            unsigned key = (v < 0.0f) ? 0u : __float_as_uint(v);
            if (key > T) nsum += v;
            else if (key == T && v >= 0.0f) ct++;
        }
        int cin = ct;
        #pragma unroll
        for (int o = 1; o < 32; o <<= 1) {
            int n2 = __shfl_up_sync(0xffffffffu, cin, o);
            if (lane >= o) cin += n2;
        }
        if (lane == 31) s_ws[wid] = cin;
        __syncthreads();
        if (wid == 0) {
            int w = s_ws[lane];
            #pragma unroll
            for (int o = 1; o < 32; o <<= 1) {
                int n2 = __shfl_up_sync(0xffffffffu, w, o);
                if (lane >= o) w += n2;
            }
            s_ws[lane] = w;
        }
        __syncthreads();
        int off0 = ((wid == 0) ? 0 : s_ws[wid - 1]) + (cin - ct);
        int r2 = 0;
        for (int i = lo; i < hi; i++) {                  // ties stable by index
            float v = s_v[i];
            unsigned key = (v < 0.0f) ? 0u : __float_as_uint(v);
            if (key == T && v >= 0.0f) {
                if (off0 + r2 < quota) nsum += v;
                r2++;
            }
        }
        if (b == 0 && tid == 0) {
            float v0 = s_v[0];
            if (v0 >= 0.0f && __float_as_uint(v0) >= T) nsum += g_ce0 - v0;
        }
    }

    s_red[tid] = ce_pos + nsum; __syncthreads();
    for (int o = 512; o > 0; o >>= 1) {
        if (tid < o) s_red[tid] += s_red[tid + o];
        __syncthreads();
    }
    if (tid == 0) {
        g_lc[b] = s_red[0];
        __threadfence();
        unsigned t = atomicAdd(&g_ticket, 1u);
        s_last = (t == B - 1);
    }
    __syncthreads();

    if (s_last) {
        __threadfence();
        float ll = 0.0f, lc = 0.0f; int npt = 0;
        if (tid < B) { ll = g_ll[tid]; lc = g_lc[tid]; npt = g_np[tid]; }
        s_red[tid] = ll; s_v[tid] = lc; cnts[tid] = npt;
        __syncthreads();
        for (int o = 64; o > 0; o >>= 1) {
            if (tid < o) { s_red[tid] += s_red[tid+o]; s_v[tid] += s_v[tid+o]; cnts[tid] += cnts[tid+o]; }
            __syncthreads();
        }
        if (tid == 0) {
            float Nf = (float)cnts[0];
            out[0] = s_red[0] / Nf;
            out[1] = s_v[0] / Nf;
        }
    }
}

// ------------- launch ----------------------------------------------------------
extern "C" void kernel_launch(void* const* d_in, const int* in_sizes, int n_in,
                              void* d_out, int out_size)
{
    const float *loc = nullptr, *conf = nullptr, *priors = nullptr, *targets = nullptr;
    for (int i = 0; i < n_in; i++) {
        long long sz = in_sizes[i];
        if      (sz == (long long)B*P*4)     loc     = (const float*)d_in[i];
        else if (sz == (long long)B*P*C)     conf    = (const float*)d_in[i];
        else if (sz == (long long)P*4)       priors  = (const float*)d_in[i];
        else if (sz == (long long)B*NOBJ*5)  targets = (const float*)d_in[i];
    }
    k_init<<<3, 1024>>>();
    k_work<<<NWORK, WT, WT*C*4>>>(conf, (const float4*)priors, targets);
    k_fix <<<B, 1024>>>(conf, (const float4*)priors, loc, targets);
    k_mine<<<B, 1024>>>((float*)d_out);
    (void)out_size;
}

// round 10
// speedup vs baseline: 1.4256x; 1.4256x over previous
#include <cuda_runtime.h>
#include <math.h>

#define B      128
#define P      8732
#define C      21
#define NOBJ   20
#define WT     512
#define NTILES 18                 // ceil(P/WT)
#define NLSE   (NTILES*B)         // 2304
#define S8     8
#define OCT    1092               // ceil(P/8)
#define NMATCH (B*S8)             // 1024
#define NWORK  (NLSE+NMATCH)      // 3328 = 13*256
#define TC     5
#define NC     (NOBJ/TC)          // 4
#define NSLOT  ((OCT+WT-1)/WT)    // 3

typedef unsigned long long ull;

__device__ ull           g_bp[B*NOBJ];
__device__ unsigned char g_code[B*P];      // bestn | pos<<7
__device__ float         g_mine[B*P];      // lse - r[0] for every prior
__device__ float         g_ll[B];
__device__ int           g_np[B];
__device__ float         g_lc[B];
__device__ unsigned      g_ticket;

__device__ __forceinline__ float sl1(float x) {
    float a = fabsf(x);
    return a < 1.0f ? 0.5f * a * a : a - 0.5f;
}

// ------------- kernel 0: init --------------------------------------------------
__global__ void k_init() {
    int i = blockIdx.x * 1024 + threadIdx.x;
    if (i < B*NOBJ) g_bp[i] = 0xFFFFFFFFull;   // key(iou=0, p=0)
    if (i == 0)     g_ticket = 0u;
}

// ------------- kernel 1: fused match (compute) + lse (DRAM) roles --------------
__global__ __launch_bounds__(WT) void k_work(const float*  __restrict__ conf,
                                             const float4* __restrict__ priors,
                                             const float*  __restrict__ targets)
{
    extern __shared__ float dsm[];
    int bx = blockIdx.x, tid = threadIdx.x;
    int grp = bx / 13, rem = bx % 13;

    if (rem < 4) {
        // ========== match role: 1024 blocks, 8 per image =======================
        ull*    s_bp   = (ull*)dsm;
        float4* s_tr4  = (float4*)(dsm + 40);
        float*  s_area = dsm + 120;

        int midx = grp*4 + rem;                // 0..1023
        int b = midx >> 3, oct = midx & 7;
        int p0 = oct * OCT;
        int cnt = min(OCT, P - p0);
        const float* tg = targets + b*NOBJ*5;
        if (tid < NOBJ) {
            float a0 = tg[tid*5+0], a1 = tg[tid*5+1];
            float a2 = tg[tid*5+2], a3 = tg[tid*5+3];
            s_tr4[tid]  = make_float4(a0, a1, a2, a3);
            s_area[tid] = (a2 - a0) * (a3 - a1);
            s_bp[tid]   = 0ull;
        }
        __syncthreads();

        float bestv[NSLOT]; int bestn[NSLOT];
        #pragma unroll
        for (int j = 0; j < NSLOT; j++) { bestv[j] = -1.0f; bestn[j] = 0; }
        int lane = tid & 31;

        for (int c = 0; c < NC; c++) {
            ull bpl[TC];
            #pragma unroll
            for (int n = 0; n < TC; n++) bpl[n] = 0ull;
            #pragma unroll
            for (int j = 0; j < NSLOT; j++) {
                int i = tid + j*WT;
                if (i < cnt) {
                    int p = p0 + i;
                    float4 pr = __ldg(priors + p);      // L1-hit after chunk 0
                    float hw = pr.z*0.5f, hh = pr.w*0.5f;
                    float bx0 = pr.x-hw, by0 = pr.y-hh;
                    float bx1 = pr.x+hw, by1 = pr.y+hh;
                    float area_b = (bx1-bx0)*(by1-by0);
                    unsigned pinv = 0xFFFFFFFFu - (unsigned)p;
                    #pragma unroll
                    for (int n5 = 0; n5 < TC; n5++) {
                        int n = c*TC + n5;
                        float4 t = s_tr4[n]; float ar = s_area[n];
                        float w = fmaxf(fminf(t.z, bx1) - fmaxf(t.x, bx0), 0.0f);
                        float h = fmaxf(fminf(t.w, by1) - fmaxf(t.y, by0), 0.0f);
                        float inter = w * h;
                        // selection-only value: fast division is safe
                        float iou = __fdividef(inter, (ar + area_b) - inter);
                        if (iou > bestv[j]) { bestv[j] = iou; bestn[j] = n; }
                        ull key = ((ull)__float_as_uint(iou) << 32) | (ull)pinv;
                        if (key > bpl[n5]) bpl[n5] = key;
                    }
                }
            }
            #pragma unroll
            for (int n5 = 0; n5 < TC; n5++) {
                ull k = bpl[n5];
                #pragma unroll
                for (int o = 16; o > 0; o >>= 1) {
                    ull x = __shfl_down_sync(0xffffffffu, k, o);
                    if (x > k) k = x;
                }
                if (lane == 0) atomicMax(&s_bp[c*TC + n5], k);
            }
        }
        #pragma unroll
        for (int j = 0; j < NSLOT; j++) {
            int i = tid + j*WT;
            if (i < cnt)
                g_code[b*P + p0 + i] =
                    (unsigned char)(bestn[j] | ((bestv[j] < 0.5f) ? 0 : 0x80));
        }
        __syncthreads();
        if (tid < NOBJ) atomicMax(&g_bp[b*NOBJ + tid], s_bp[tid]);
    } else {
        // ========== lse role: 2304 blocks, float4 streaming ====================
        float* s_stage = dsm;                  // WT*C floats = 43008 B
        int lidx = grp*9 + (rem - 4);
        int b = lidx / NTILES, tile = lidx % NTILES;
        int t0 = tile * WT, rows = min(WT, P - t0);
        int elems = rows * C;
        size_t base_f = ((size_t)b*P + t0) * C;
        size_t a0 = (base_f + 3) & ~(size_t)3;         // first 16B-aligned float
        int head = (int)(a0 - base_f);                  // 0..3
        if (tid < head) s_stage[tid] = __ldg(conf + base_f + tid);
        int rest = elems - head;
        int nq = rest >> 2;                             // full quads
        const float4* cq = (const float4*)conf + (a0 >> 2);
        for (int q = tid; q < nq; q += WT) {
            float4 v = __ldg(cq + q);
            int s = head + q*4;
            s_stage[s+0] = v.x; s_stage[s+1] = v.y;
            s_stage[s+2] = v.z; s_stage[s+3] = v.w;
        }
        int tstart = head + nq*4;
        if (tid < elems - tstart)                       // 0..3 tail scalars
            s_stage[tstart + tid] = __ldg(conf + base_f + tstart + tid);
        __syncthreads();
        if (tid < rows) {
            const float* r = s_stage + tid * C;         // stride 21: conflict-free
            float mx = r[0];
            #pragma unroll
            for (int c2 = 1; c2 < C; c2++) mx = fmaxf(mx, r[c2]);
            float s = 0.0f;
            #pragma unroll
            for (int c2 = 0; c2 < C; c2++) s += __expf(r[c2] - mx);
            float lse = mx + __logf(s);
            g_mine[(size_t)b*P + t0 + tid] = lse - r[0];
        }
    }
}

// ------------- kernel 2: fixup + hard-negative mining + final ------------------
// dynamic smem layout
#define MOFF_V     0                       // P floats
#define MOFF_CODE  (MOFF_V + P*4)          // P bytes
#define MOFF_RED   ((MOFF_CODE + P + 15) & ~15)   // 1024 floats
#define MOFF_CNT   (MOFF_RED + 1024*4)     // 1056 ints
#define MOFF_HIST  (MOFF_CNT + 1056*4)     // 256 ints
#define MOFF_TR    (MOFF_HIST + 256*4)     // 100 floats
#define MOFF_P2    (MOFF_TR + 100*4)       // 20 ints
#define MOFF_SCAL  (MOFF_P2 + 20*4)        // 4 words
#define MSMEM      (MOFF_SCAL + 16)

__global__ __launch_bounds__(1024) void k_minefix(const float*  __restrict__ conf,
                                                  const float4* __restrict__ priors,
                                                  const float*  __restrict__ loc,
                                                  const float*  __restrict__ targets,
                                                  float* __restrict__ out)
{
    extern __shared__ unsigned char msm[];
    float*         s_v    = (float*)(msm + MOFF_V);
    unsigned char* s_code = msm + MOFF_CODE;
    float*         s_red  = (float*)(msm + MOFF_RED);
    int*           cnts   = (int*)  (msm + MOFF_CNT);
    int*           hist   = (int*)  (msm + MOFF_HIST);
    float*         s_tr   = (float*)(msm + MOFF_TR);
    int*           s_p2   = (int*)  (msm + MOFF_P2);
    unsigned*      s_pref = (unsigned*)(msm + MOFF_SCAL);
    int*           s_klft = (int*)  (msm + MOFF_SCAL + 4);
    float*         s_ce0  = (float*)(msm + MOFF_SCAL + 8);
    int*           s_last = (int*)  (msm + MOFF_SCAL + 12);
    int* s_ws = cnts + 1024;

    int b = blockIdx.x, tid = threadIdx.x;
    int lane = tid & 31, wid = tid >> 5;

    // load mining values (float4: P%4==0) and code bytes
    const float4* gm4 = (const float4*)(g_mine + (size_t)b*P);
    float4* sv4 = (float4*)s_v;
    for (int i = tid; i < P/4; i += 1024) sv4[i] = gm4[i];
    const unsigned* gc = (const unsigned*)(g_code + b*P);
    unsigned* sc = (unsigned*)s_code;
    for (int i = tid; i < P/4; i += 1024) sc[i] = gc[i];
    if (tid < NOBJ*5) s_tr[tid] = targets[b*NOBJ*5 + tid];
    if (tid < NOBJ)
        s_p2[tid] = (int)(0xFFFFFFFFu - (unsigned)(g_bp[b*NOBJ + tid] & 0xFFFFFFFFull));
    __syncthreads();
    if (tid == 0) {   // ascending m, last write wins = JAX "chosen = max n"
        for (int m = 0; m < NOBJ; m++) s_code[s_p2[m]] = (unsigned char)(m | 0x80);
    }
    __syncthreads();

    // ---- fixup: positives -> ce into accumulator, s_v[p] = -1; loc loss ------
    float ll = 0.0f, ce_pos = 0.0f; int np = 0;
    for (int p = tid; p < P; p += 1024) {
        unsigned char code = s_code[p];
        size_t idx = (size_t)b*P + p;
        if (code & 0x80) {
            int n = code & 31;
            np++;
            int cf = (int)s_tr[n*5+4] + 1;
            float r0  = __ldg(conf + idx*C);
            float rcf = __ldg(conf + idx*C + cf);
            ce_pos += s_v[p] + r0 - rcf;               // (lse-r0)+r0-rcf
            s_v[p] = -1.0f;
            float4 pr = __ldg(priors + p);
            float a0 = s_tr[n*5+0], a1 = s_tr[n*5+1];
            float a2 = s_tr[n*5+2], a3 = s_tr[n*5+3];
            float gx = ((a0 + a2) * 0.5f - pr.x) / (0.1f * pr.z);
            float gy = ((a1 + a3) * 0.5f - pr.y) / (0.1f * pr.w);
            float gw = logf((a2 - a0) / pr.z) * 5.0f;
            float gh = logf((a3 - a1) / pr.w) * 5.0f;
            float4 ld = __ldg(((const float4*)loc) + idx);
            ll += sl1(ld.x - gx) + sl1(ld.y - gy) + sl1(ld.z - gw) + sl1(ld.w - gh);
        } else if (b == 0 && p == 0) {
            // clamped[0]=1 quirk: recompute lse with IDENTICAL op sequence
            float rr[C];
            #pragma unroll
            for (int c2 = 0; c2 < C; c2++) rr[c2] = __ldg(conf + c2);
            float mx = rr[0];
            #pragma unroll
            for (int c2 = 1; c2 < C; c2++) mx = fmaxf(mx, rr[c2]);
            float s = 0.0f;
            #pragma unroll
            for (int c2 = 0; c2 < C; c2++) s += __expf(rr[c2] - mx);
            float lse = mx + __logf(s);
            *s_ce0 = lse - rr[0];                      // true CE if selected
            s_v[0] = lse - rr[1];                      // mining value uses class 1
        }
    }
    // reduce np (mining needs it before select)
    cnts[tid] = np; __syncthreads();
    for (int o = 512; o > 0; o >>= 1) {
        if (tid < o) cnts[tid] += cnts[tid + o];
        __syncthreads();
    }
    int np_tot = cnts[0];
    __syncthreads();

    // ---- mining: exact top-k radix select (plain smem atomics, R8 style) -----
    int k = 3 * np_tot; if (k > P - 1) k = P - 1;
    int negc = P - np_tot;
    const int CH = (P + 1023) / 1024;                  // 9
    int lo = tid * CH, hi = min(lo + CH, P);
    float nsum = 0.0f;

    if (k >= negc) {
        for (int i = lo; i < hi; i++) { float v = s_v[i]; if (v >= 0.0f) nsum += v; }
        if (b == 0 && tid == 0) { float v0 = s_v[0]; if (v0 >= 0.0f) nsum += *s_ce0 - v0; }
    } else {
        unsigned pref = 0; int kleft = k;
        for (int shift = 24; shift >= 0; shift -= 8) {
            if (tid < 256) hist[tid] = 0;
            __syncthreads();
            for (int i = lo; i < hi; i++) {
                float v = s_v[i];
                unsigned key = (v < 0.0f) ? 0u : __float_as_uint(v);
                unsigned kh = key >> shift;
                bool ok = (shift == 24) || ((kh >> 8) == pref);
                if (ok) atomicAdd(&hist[kh & 255u], 1);
            }
            __syncthreads();
            if (wid == 0) {                            // warp-only bin select
                int c[8]; int tot = 0;
                #pragma unroll
                for (int j = 0; j < 8; j++) { c[j] = hist[lane*8 + j]; tot += c[j]; }
                int suf = tot;
                #pragma unroll
                for (int o = 1; o < 32; o <<= 1) {
                    int y = __shfl_down_sync(0xffffffffu, suf, o);
                    if (lane + o < 32) suf += y;
                }
                int cum = suf - tot;
                #pragma unroll
                for (int j = 7; j >= 0; j--) {
                    if (cum < kleft && cum + c[j] >= kleft) {
                        *s_pref = (pref << 8) | (unsigned)(lane*8 + j);
                        *s_klft = kleft - cum;
                    }
                    cum += c[j];
                }
            }
            __syncthreads();
            pref = *s_pref; kleft = *s_klft;
        }
        unsigned T = pref; int quota = kleft;          // quota >= 1

        int ct = 0;
        for (int i = lo; i < hi; i++) {
            float v = s_v[i];
            unsigned key = (v < 0.0f) ? 0u : __float_as_uint(v);
            if (key > T) nsum += v;
            else if (key == T && v >= 0.0f) ct++;
        }
        int cin = ct;
        #pragma unroll
        for (int o = 1; o < 32; o <<= 1) {
            int n2 = __shfl_up_sync(0xffffffffu, cin, o);
            if (lane >= o) cin += n2;
        }
        if (lane == 31) s_ws[wid] = cin;
        __syncthreads();
        if (wid == 0) {
            int w = s_ws[lane];
            #pragma unroll
            for (int o = 1; o < 32; o <<= 1) {
                int n2 = __shfl_up_sync(0xffffffffu, w, o);
                if (lane >= o) w += n2;
            }
            s_ws[lane] = w;
        }
        __syncthreads();
        int off0 = ((wid == 0) ? 0 : s_ws[wid - 1]) + (cin - ct);
        int r2 = 0;
        for (int i = lo; i < hi; i++) {                // ties stable by index
            float v = s_v[i];
            unsigned key = (v < 0.0f) ? 0u : __float_as_uint(v);
            if (key == T && v >= 0.0f) {
                if (off0 + r2 < quota) nsum += v;
                r2++;
            }
        }
        if (b == 0 && tid == 0) {
            float v0 = s_v[0];
            if (v0 >= 0.0f && __float_as_uint(v0) >= T) nsum += *s_ce0 - v0;
        }
    }

    // ---- reduce ll and lc, write per-image partials ---------------------------
    s_red[tid] = ce_pos + nsum; __syncthreads();
    for (int o = 512; o > 0; o >>= 1) {
        if (tid < o) s_red[tid] += s_red[tid + o];
        __syncthreads();
    }
    float lc_tot = s_red[0];
    __syncthreads();
    s_red[tid] = ll; __syncthreads();
    for (int o = 512; o > 0; o >>= 1) {
        if (tid < o) s_red[tid] += s_red[tid + o];
        __syncthreads();
    }
    if (tid == 0) {
        g_ll[b] = s_red[0]; g_lc[b] = lc_tot; g_np[b] = np_tot;
        __threadfence();
        unsigned t = atomicAdd(&g_ticket, 1u);
        *s_last = (t == B - 1);
    }
    __syncthreads();

    if (*s_last) {                                     // last block: final reduce
        __threadfence();
        float llg = 0.0f, lcg = 0.0f; int npg = 0;
        if (tid < B) { llg = g_ll[tid]; lcg = g_lc[tid]; npg = g_np[tid]; }
        s_red[tid] = llg; s_v[tid] = lcg; cnts[tid] = npg;
        __syncthreads();
        for (int o = 64; o > 0; o >>= 1) {
            if (tid < o) { s_red[tid] += s_red[tid+o]; s_v[tid] += s_v[tid+o]; cnts[tid] += cnts[tid+o]; }
            __syncthreads();
        }
        if (tid == 0) {
            float Nf = (float)cnts[0];
            out[0] = s_red[0] / Nf;
            out[1] = s_v[0] / Nf;
        }
    }
}

// ------------- launch ------------------------------------------------------------
extern "C" void kernel_launch(void* const* d_in, const int* in_sizes, int n_in,
                              void* d_out, int out_size)
{
    const float *loc = nullptr, *conf = nullptr, *priors = nullptr, *targets = nullptr;
    for (int i = 0; i < n_in; i++) {
        long long sz = in_sizes[i];
        if      (sz == (long long)B*P*4)     loc     = (const float*)d_in[i];
        else if (sz == (long long)B*P*C)     conf    = (const float*)d_in[i];
        else if (sz == (long long)P*4)       priors  = (const float*)d_in[i];
        else if (sz == (long long)B*NOBJ*5)  targets = (const float*)d_in[i];
    }
    static int attr_done = 0;
    if (!attr_done) {
        cudaFuncSetAttribute(k_minefix, cudaFuncAttributeMaxDynamicSharedMemorySize, MSMEM);
        attr_done = 1;
    }
    k_init   <<<3, 1024>>>();
    k_work   <<<NWORK, WT, WT*C*4>>>(conf, (const float4*)priors, targets);
    k_minefix<<<B, 1024, MSMEM>>>(conf, (const float4*)priors, loc, targets, (float*)d_out);
    (void)out_size;
}

// round 11
// speedup vs baseline: 1.4814x; 1.0392x over previous
#include <cuda_runtime.h>
#include <math.h>

#define B      128
#define P      8732
#define C      21
#define NOBJ   20
#define WT     512
#define S8     8
#define OCT    1092               // ceil(P/8)
#define TC     5
#define NC     (NOBJ/TC)          // 4
#define NSLOT  ((OCT+WT-1)/WT)    // 3
#define LROWS  384                // lse rows per block
#define LTILES ((P + LROWS - 1)/LROWS)   // 23
#define GROUP  (S8 + LTILES)      // 31 blocks per image
#define NWORK  (B*GROUP)          // 3968
#define LBYTES (LROWS*C*4)        // 32256 B dynamic smem

typedef unsigned long long ull;

__device__ ull           g_bp2[B*S8*NOBJ];  // per-(image,oct,truth) best key (plain stores)
__device__ unsigned char g_code[B*P];       // bestn | pos<<7
__device__ float         g_mine[B*P];       // lse - r[0] for every prior
__device__ float         g_ll[B];
__device__ int           g_np[B];
__device__ float         g_lc[B];
__device__ unsigned      g_ticket;          // never reset: mod-B phase invariant

__device__ __forceinline__ float sl1(float x) {
    float a = fabsf(x);
    return a < 1.0f ? 0.5f * a * a : a - 0.5f;
}

// ------------- kernel 1: fused match (compute) + lse (DRAM) roles --------------
__global__ __launch_bounds__(WT) void k_work(const float*  __restrict__ conf,
                                             const float4* __restrict__ priors,
                                             const float*  __restrict__ targets)
{
    extern __shared__ float dsm[];
    int bx = blockIdx.x, tid = threadIdx.x;
    int b = bx / GROUP, rem = bx % GROUP;

    if (rem < S8) {
        // ========== match role: 8 blocks per image =============================
        ull*    s_bp   = (ull*)dsm;            // 20 ull
        float4* s_tr4  = (float4*)(dsm + 40);  // 20 f4
        float*  s_area = dsm + 120;            // 20 f

        int oct = rem;
        int p0 = oct * OCT;
        int cnt = min(OCT, P - p0);
        const float* tg = targets + b*NOBJ*5;
        if (tid < NOBJ) {
            float a0 = tg[tid*5+0], a1 = tg[tid*5+1];
            float a2 = tg[tid*5+2], a3 = tg[tid*5+3];
            s_tr4[tid]  = make_float4(a0, a1, a2, a3);
            s_area[tid] = (a2 - a0) * (a3 - a1);
            s_bp[tid]   = 0ull;
        }
        __syncthreads();

        float bestv[NSLOT]; int bestn[NSLOT];
        #pragma unroll
        for (int j = 0; j < NSLOT; j++) { bestv[j] = -1.0f; bestn[j] = 0; }
        int lane = tid & 31;

        for (int c = 0; c < NC; c++) {         // truth chunks of 5 -> low regs
            ull bpl[TC];
            #pragma unroll
            for (int n = 0; n < TC; n++) bpl[n] = 0ull;
            #pragma unroll
            for (int j = 0; j < NSLOT; j++) {
                int i = tid + j*WT;
                if (i < cnt) {
                    int p = p0 + i;
                    float4 pr = __ldg(priors + p);      // L1-hit after chunk 0
                    float hw = pr.z*0.5f, hh = pr.w*0.5f;
                    float bx0 = pr.x-hw, by0 = pr.y-hh;
                    float bx1 = pr.x+hw, by1 = pr.y+hh;
                    float area_b = (bx1-bx0)*(by1-by0);
                    unsigned pinv = 0xFFFFFFFFu - (unsigned)p;
                    #pragma unroll
                    for (int n5 = 0; n5 < TC; n5++) {
                        int n = c*TC + n5;
                        float4 t = s_tr4[n]; float ar = s_area[n];
                        float w = fmaxf(fminf(t.z, bx1) - fmaxf(t.x, bx0), 0.0f);
                        float h = fmaxf(fminf(t.w, by1) - fmaxf(t.y, by0), 0.0f);
                        float inter = w * h;
                        // selection-only value: fast division is safe
                        float iou = __fdividef(inter, (ar + area_b) - inter);
                        if (iou > bestv[j]) { bestv[j] = iou; bestn[j] = n; }
                        ull key = ((ull)__float_as_uint(iou) << 32) | (ull)pinv;
                        if (key > bpl[n5]) bpl[n5] = key;
                    }
                }
            }
            #pragma unroll
            for (int n5 = 0; n5 < TC; n5++) {
                ull k = bpl[n5];
                #pragma unroll
                for (int o = 16; o > 0; o >>= 1) {
                    ull x = __shfl_down_sync(0xffffffffu, k, o);
                    if (x > k) k = x;
                }
                if (lane == 0) atomicMax(&s_bp[c*TC + n5], k);
            }
        }
        #pragma unroll
        for (int j = 0; j < NSLOT; j++) {
            int i = tid + j*WT;
            if (i < cnt)
                g_code[b*P + p0 + i] =
                    (unsigned char)(bestn[j] | ((bestv[j] < 0.5f) ? 0 : 0x80));
        }
        __syncthreads();
        // plain store into this block's private slot: no init, no global atomics
        if (tid < NOBJ) g_bp2[(b*S8 + oct)*NOBJ + tid] = s_bp[tid];
    } else {
        // ========== lse role: 23 blocks per image, float4 streaming ============
        float* s_stage = dsm;                  // LROWS*C floats = 32256 B
        int tile = rem - S8;
        int t0 = tile * LROWS, rows = min(LROWS, P - t0);
        int elems = rows * C;
        size_t base_f = ((size_t)b*P + t0) * C;
        size_t a0 = (base_f + 3) & ~(size_t)3;         // first 16B-aligned float
        int head = (int)(a0 - base_f);                  // 0..3
        if (tid < head) s_stage[tid] = __ldg(conf + base_f + tid);
        int rest = elems - head;
        int nq = rest >> 2;                             // full quads
        const float4* cq = (const float4*)conf + (a0 >> 2);
        for (int q = tid; q < nq; q += WT) {
            float4 v = __ldg(cq + q);
            int s = head + q*4;
            s_stage[s+0] = v.x; s_stage[s+1] = v.y;
            s_stage[s+2] = v.z; s_stage[s+3] = v.w;
        }
        int tstart = head + nq*4;
        if (tid < elems - tstart)                       // 0..3 tail scalars
            s_stage[tstart + tid] = __ldg(conf + base_f + tstart + tid);
        __syncthreads();
        if (tid < rows) {
            const float* r = s_stage + tid * C;         // stride 21: conflict-free
            float mx = r[0];
            #pragma unroll
            for (int c2 = 1; c2 < C; c2++) mx = fmaxf(mx, r[c2]);
            float s = 0.0f;
            #pragma unroll
            for (int c2 = 0; c2 < C; c2++) s += __expf(r[c2] - mx);
            float lse = mx + __logf(s);
            g_mine[(size_t)b*P + t0 + tid] = lse - r[0];
        }
    }
}

// ------------- kernel 2: fixup + hard-negative mining + final ------------------
#define HC         8                         // histogram copies
#define MOFF_V     0                         // P floats
#define MOFF_CODE  (MOFF_V + P*4)            // P bytes
#define MOFF_RED   ((MOFF_CODE + P + 15) & ~15)  // 1024 floats
#define MOFF_CNT   (MOFF_RED + 1024*4)       // 1056 ints
#define MOFF_HIST  (MOFF_CNT + 1056*4)       // HC*256 ints
#define MOFF_HC    (MOFF_HIST + HC*256*4)    // 256 ints combined
#define MOFF_TR    (MOFF_HC + 256*4)         // 100 floats
#define MOFF_P2    (MOFF_TR + 100*4)         // 20 ints
#define MOFF_SCAL  (MOFF_P2 + 20*4)          // 4 words
#define MSMEM      (MOFF_SCAL + 16)

__global__ __launch_bounds__(1024) void k_minefix(const float*  __restrict__ conf,
                                                  const float4* __restrict__ priors,
                                                  const float*  __restrict__ loc,
                                                  const float*  __restrict__ targets,
                                                  float* __restrict__ out)
{
    extern __shared__ unsigned char msm[];
    float*         s_v    = (float*)(msm + MOFF_V);
    unsigned char* s_code = msm + MOFF_CODE;
    float*         s_red  = (float*)(msm + MOFF_RED);
    int*           cnts   = (int*)  (msm + MOFF_CNT);
    int*           hist   = (int*)  (msm + MOFF_HIST);
    int*           histC  = (int*)  (msm + MOFF_HC);
    float*         s_tr   = (float*)(msm + MOFF_TR);
    int*           s_p2   = (int*)  (msm + MOFF_P2);
    unsigned*      s_pref = (unsigned*)(msm + MOFF_SCAL);
    int*           s_klft = (int*)  (msm + MOFF_SCAL + 4);
    float*         s_ce0  = (float*)(msm + MOFF_SCAL + 8);
    int*           s_last = (int*)  (msm + MOFF_SCAL + 12);
    int* s_ws = cnts + 1024;

    int b = blockIdx.x, tid = threadIdx.x;
    int lane = tid & 31, wid = tid >> 5;

    // load mining values (float4: P%4==0) and code bytes
    const float4* gm4 = (const float4*)(g_mine + (size_t)b*P);
    float4* sv4 = (float4*)s_v;
    for (int i = tid; i < P/4; i += 1024) sv4[i] = gm4[i];
    const unsigned* gc = (const unsigned*)(g_code + b*P);
    unsigned* sc = (unsigned*)s_code;
    for (int i = tid; i < P/4; i += 1024) sc[i] = gc[i];
    if (tid < NOBJ*5) s_tr[tid] = targets[b*NOBJ*5 + tid];
    if (tid < NOBJ) {
        ull k = 0ull;                         // reduce 8 per-oct slots
        #pragma unroll
        for (int o = 0; o < S8; o++) {
            ull x = g_bp2[(b*S8 + o)*NOBJ + tid];
            if (x > k) k = x;
        }
        s_p2[tid] = (int)(0xFFFFFFFFu - (unsigned)(k & 0xFFFFFFFFull));
    }
    __syncthreads();
    if (tid == 0) {   // ascending m, last write wins = JAX "chosen = max n"
        for (int m = 0; m < NOBJ; m++) s_code[s_p2[m]] = (unsigned char)(m | 0x80);
    }
    __syncthreads();

    // ---- fixup: positives -> ce into accumulator, s_v[p] = -1; loc loss ------
    float ll = 0.0f, ce_pos = 0.0f; int np = 0;
    for (int p = tid; p < P; p += 1024) {
        unsigned char code = s_code[p];
        size_t idx = (size_t)b*P + p;
        if (code & 0x80) {
            int n = code & 31;
            np++;
            int cf = (int)s_tr[n*5+4] + 1;
            float r0  = __ldg(conf + idx*C);
            float rcf = __ldg(conf + idx*C + cf);
            ce_pos += s_v[p] + r0 - rcf;               // (lse-r0)+r0-rcf
            s_v[p] = -1.0f;
            float4 pr = __ldg(priors + p);
            float a0 = s_tr[n*5+0], a1 = s_tr[n*5+1];
            float a2 = s_tr[n*5+2], a3 = s_tr[n*5+3];
            float gx = ((a0 + a2) * 0.5f - pr.x) / (0.1f * pr.z);
            float gy = ((a1 + a3) * 0.5f - pr.y) / (0.1f * pr.w);
            float gw = logf((a2 - a0) / pr.z) * 5.0f;
            float gh = logf((a3 - a1) / pr.w) * 5.0f;
            float4 ld = __ldg(((const float4*)loc) + idx);
            ll += sl1(ld.x - gx) + sl1(ld.y - gy) + sl1(ld.z - gw) + sl1(ld.w - gh);
        } else if (b == 0 && p == 0) {
            // clamped[0]=1 quirk: recompute lse with IDENTICAL op sequence
            float rr[C];
            #pragma unroll
            for (int c2 = 0; c2 < C; c2++) rr[c2] = __ldg(conf + c2);
            float mx = rr[0];
            #pragma unroll
            for (int c2 = 1; c2 < C; c2++) mx = fmaxf(mx, rr[c2]);
            float s = 0.0f;
            #pragma unroll
            for (int c2 = 0; c2 < C; c2++) s += __expf(rr[c2] - mx);
            float lse = mx + __logf(s);
            *s_ce0 = lse - rr[0];                      // true CE if selected
            s_v[0] = lse - rr[1];                      // mining value uses class 1
        }
    }
    // reduce np (mining needs it before select)
    cnts[tid] = np; __syncthreads();
    for (int o = 512; o > 0; o >>= 1) {
        if (tid < o) cnts[tid] += cnts[tid + o];
        __syncthreads();
    }
    int np_tot = cnts[0];
    __syncthreads();

    // ---- mining: exact top-k radix select, 8-way privatized histograms -------
    int k = 3 * np_tot; if (k > P - 1) k = P - 1;
    int negc = P - np_tot;
    const int CH = (P + 1023) / 1024;                  // 9
    int lo = tid * CH, hi = min(lo + CH, P);
    float nsum = 0.0f;
    int* myhist = hist + (wid & (HC-1)) * 256;

    if (k >= negc) {
        for (int i = lo; i < hi; i++) { float v = s_v[i]; if (v >= 0.0f) nsum += v; }
        if (b == 0 && tid == 0) { float v0 = s_v[0]; if (v0 >= 0.0f) nsum += *s_ce0 - v0; }
    } else {
        unsigned pref = 0; int kleft = k;
        for (int shift = 24; shift >= 0; shift -= 8) {
            for (int i = tid; i < HC*256; i += 1024) hist[i] = 0;
            __syncthreads();
            for (int i = lo; i < hi; i++) {
                float v = s_v[i];
                unsigned key = (v < 0.0f) ? 0u : __float_as_uint(v);
                unsigned kh = key >> shift;
                bool ok = (shift == 24) || ((kh >> 8) == pref);
                if (ok) atomicAdd(&myhist[kh & 255u], 1);
            }
            __syncthreads();
            if (tid < 256) {
                int s = 0;
                #pragma unroll
                for (int c2 = 0; c2 < HC; c2++) s += hist[c2*256 + tid];
                histC[tid] = s;
            }
            __syncthreads();
            if (wid == 0) {                            // warp-only bin select
                int c[8]; int tot = 0;
                #pragma unroll
                for (int j = 0; j < 8; j++) { c[j] = histC[lane*8 + j]; tot += c[j]; }
                int suf = tot;
                #pragma unroll
                for (int o = 1; o < 32; o <<= 1) {
                    int y = __shfl_down_sync(0xffffffffu, suf, o);
                    if (lane + o < 32) suf += y;
                }
                int cum = suf - tot;
                #pragma unroll
                for (int j = 7; j >= 0; j--) {
                    if (cum < kleft && cum + c[j] >= kleft) {
                        *s_pref = (pref << 8) | (unsigned)(lane*8 + j);
                        *s_klft = kleft - cum;
                    }
                    cum += c[j];
                }
            }
            __syncthreads();
            pref = *s_pref; kleft = *s_klft;
        }
        unsigned T = pref; int quota = kleft;          // quota >= 1

        int ct = 0;
        for (int i = lo; i < hi; i++) {
            float v = s_v[i];
            unsigned key = (v < 0.0f) ? 0u : __float_as_uint(v);
            if (key > T) nsum += v;
            else if (key == T && v >= 0.0f) ct++;
        }
        int cin = ct;
        #pragma unroll
        for (int o = 1; o < 32; o <<= 1) {
            int n2 = __shfl_up_sync(0xffffffffu, cin, o);
            if (lane >= o) cin += n2;
        }
        if (lane == 31) s_ws[wid] = cin;
        __syncthreads();
        if (wid == 0) {
            int w = s_ws[lane];
            #pragma unroll
            for (int o = 1; o < 32; o <<= 1) {
                int n2 = __shfl_up_sync(0xffffffffu, w, o);
                if (lane >= o) w += n2;
            }
            s_ws[lane] = w;
        }
        __syncthreads();
        int off0 = ((wid == 0) ? 0 : s_ws[wid - 1]) + (cin - ct);
        int r2 = 0;
        for (int i = lo; i < hi; i++) {                // ties stable by index
            float v = s_v[i];
            unsigned key = (v < 0.0f) ? 0u : __float_as_uint(v);
            if (key == T && v >= 0.0f) {
                if (off0 + r2 < quota) nsum += v;
                r2++;
            }
        }
        if (b == 0 && tid == 0) {
            float v0 = s_v[0];
            if (v0 >= 0.0f && __float_as_uint(v0) >= T) nsum += *s_ce0 - v0;
        }
    }

    // ---- reduce ll and lc, write per-image partials ---------------------------
    s_red[tid] = ce_pos + nsum; __syncthreads();
    for (int o = 512; o > 0; o >>= 1) {
        if (tid < o) s_red[tid] += s_red[tid + o];
        __syncthreads();
    }
    float lc_tot = s_red[0];
    __syncthreads();
    s_red[tid] = ll; __syncthreads();
    for (int o = 512; o > 0; o >>= 1) {
        if (tid < o) s_red[tid] += s_red[tid + o];
        __syncthreads();
    }
    if (tid == 0) {
        g_ll[b] = s_red[0]; g_lc[b] = lc_tot; g_np[b] = np_tot;
        __threadfence();
        unsigned t = atomicAdd(&g_ticket, 1u);
        *s_last = ((t % B) == B - 1);                  // phase-correct, no reset
    }
    __syncthreads();

    if (*s_last) {                                     // last block: final reduce
        __threadfence();
        float llg = 0.0f, lcg = 0.0f; int npg = 0;
        if (tid < B) { llg = g_ll[tid]; lcg = g_lc[tid]; npg = g_np[tid]; }
        s_red[tid] = llg; s_v[tid] = lcg; cnts[tid] = npg;
        __syncthreads();
        for (int o = 64; o > 0; o >>= 1) {
            if (tid < o) { s_red[tid] += s_red[tid+o]; s_v[tid] += s_v[tid+o]; cnts[tid] += cnts[tid+o]; }
            __syncthreads();
        }
        if (tid == 0) {
            float Nf = (float)cnts[0];
            out[0] = s_red[0] / Nf;
            out[1] = s_v[0] / Nf;
        }
    }
}

// ------------- launch ------------------------------------------------------------
extern "C" void kernel_launch(void* const* d_in, const int* in_sizes, int n_in,
                              void* d_out, int out_size)
{
    const float *loc = nullptr, *conf = nullptr, *priors = nullptr, *targets = nullptr;
    for (int i = 0; i < n_in; i++) {
        long long sz = in_sizes[i];
        if      (sz == (long long)B*P*4)     loc     = (const float*)d_in[i];
        else if (sz == (long long)B*P*C)     conf    = (const float*)d_in[i];
        else if (sz == (long long)P*4)       priors  = (const float*)d_in[i];
        else if (sz == (long long)B*NOBJ*5)  targets = (const float*)d_in[i];
    }
    static int attr_done = 0;
    if (!attr_done) {
        cudaFuncSetAttribute(k_minefix, cudaFuncAttributeMaxDynamicSharedMemorySize, MSMEM);
        attr_done = 1;
    }
    k_work   <<<NWORK, WT, LBYTES>>>(conf, (const float4*)priors, targets);
    k_minefix<<<B, 1024, MSMEM>>>(conf, (const float4*)priors, loc, targets, (float*)d_out);
    (void)out_size;
}

// round 12
// speedup vs baseline: 1.7134x; 1.1566x over previous
#include <cuda_runtime.h>
#include <math.h>

#define B      128
#define P      8732
#define C      21
#define NOBJ   20
#define WT     512
#define S2     2
#define HALF   (P/2)              // 4366
#define HSLOT  ((HALF+WT-1)/WT)   // 9
#define TC     5
#define NC     (NOBJ/TC)          // 4
#define LROWS  384
#define LTILES ((P + LROWS - 1)/LROWS)   // 23
#define GROUP  (S2 + LTILES)      // 25 blocks per image
#define NWORK  (B*GROUP)          // 3200
#define LBYTES (LROWS*C*4)        // 32256 B dynamic smem

typedef unsigned long long ull;

__device__ ull           g_bp2[B*S2*NOBJ];  // per-(image,half,truth) best key
__device__ unsigned char g_code[B*P];       // bestn | pos<<7
__device__ float         g_mine[B*P];       // lse - r[0] for every prior
__device__ float         g_ll[B];
__device__ int           g_np[B];
__device__ float         g_lc[B];
__device__ unsigned      g_ticket;          // never reset: mod-B phase invariant

__device__ __forceinline__ float sl1(float x) {
    float a = fabsf(x);
    return a < 1.0f ? 0.5f * a * a : a - 0.5f;
}

// ------------- kernel 1: fused match (compute) + lse (DRAM) roles --------------
__global__ __launch_bounds__(WT) void k_work(const float*  __restrict__ conf,
                                             const float4* __restrict__ priors,
                                             const float*  __restrict__ targets)
{
    extern __shared__ float dsm[];
    int bx = blockIdx.x, tid = threadIdx.x;
    int b = bx / GROUP, rem = bx % GROUP;

    if (rem < S2) {
        // ========== match role: 2 blocks per image =============================
        ull*    s_bp   = (ull*)dsm;            // 20 ull
        float4* s_tr4  = (float4*)(dsm + 40);  // 20 f4
        float*  s_area = dsm + 120;            // 20 f

        int half = rem;
        int p0 = half * HALF;
        const float* tg = targets + b*NOBJ*5;
        if (tid < NOBJ) {
            float a0 = tg[tid*5+0], a1 = tg[tid*5+1];
            float a2 = tg[tid*5+2], a3 = tg[tid*5+3];
            s_tr4[tid]  = make_float4(a0, a1, a2, a3);
            s_area[tid] = (a2 - a0) * (a3 - a1);
            s_bp[tid]   = 0xFFFFFFFFull;       // floor key: (iou=0, p=0)
        }
        __syncthreads();

        float bestv[HSLOT]; int bestn[HSLOT];
        #pragma unroll
        for (int j = 0; j < HSLOT; j++) { bestv[j] = -1.0f; bestn[j] = 0; }
        int lane = tid & 31;

        for (int c = 0; c < NC; c++) {         // truth chunks of 5 -> low regs
            float    bi[TC];
            unsigned bp_[TC];
            #pragma unroll
            for (int n = 0; n < TC; n++) { bi[n] = 0.0f; bp_[n] = 0xFFFFFFFFu; }
            #pragma unroll
            for (int j = 0; j < HSLOT; j++) {
                int i = tid + j*WT;
                if (i < HALF) {
                    int p = p0 + i;
                    float4 pr = __ldg(priors + p);      // L1-hit after chunk 0
                    float hw = pr.z*0.5f, hh = pr.w*0.5f;
                    float bx0 = pr.x-hw, by0 = pr.y-hh;
                    float bx1 = pr.x+hw, by1 = pr.y+hh;
                    float area_b = (bx1-bx0)*(by1-by0);
                    #pragma unroll
                    for (int n5 = 0; n5 < TC; n5++) {
                        int n = c*TC + n5;
                        float4 t = s_tr4[n];
                        float w = fmaxf(fminf(t.z, bx1) - fmaxf(t.x, bx0), 0.0f);
                        float h = fmaxf(fminf(t.w, by1) - fmaxf(t.y, by0), 0.0f);
                        float inter = w * h;
                        if (inter > 0.0f) {             // warp-coherent skip
                            float iou = __fdividef(inter, (s_area[n] + area_b) - inter);
                            if (iou > bestv[j]) { bestv[j] = iou; bestn[j] = n; }
                            // p ascends in j => strict > keeps earliest p (ties)
                            if (iou > bi[n5]) { bi[n5] = iou; bp_[n5] = (unsigned)p; }
                        }
                    }
                }
            }
            #pragma unroll
            for (int n5 = 0; n5 < TC; n5++) {           // key built ONCE per chunk
                ull k = ((ull)__float_as_uint(bi[n5]) << 32) | (ull)(~bp_[n5]);
                #pragma unroll
                for (int o = 16; o > 0; o >>= 1) {
                    ull x = __shfl_down_sync(0xffffffffu, k, o);
                    if (x > k) k = x;
                }
                if (lane == 0) atomicMax(&s_bp[c*TC + n5], k);
            }
        }
        #pragma unroll
        for (int j = 0; j < HSLOT; j++) {
            int i = tid + j*WT;
            if (i < HALF)
                g_code[b*P + p0 + i] =
                    (unsigned char)(bestn[j] | ((bestv[j] < 0.5f) ? 0 : 0x80));
        }
        __syncthreads();
        if (tid < NOBJ) g_bp2[(b*S2 + half)*NOBJ + tid] = s_bp[tid];
    } else {
        // ========== lse role: 23 blocks per image, float4 streaming ============
        float* s_stage = dsm;                  // LROWS*C floats = 32256 B
        int tile = rem - S2;
        int t0 = tile * LROWS, rows = min(LROWS, P - t0);
        int elems = rows * C;
        size_t base_f = ((size_t)b*P + t0) * C;
        size_t a0 = (base_f + 3) & ~(size_t)3;         // first 16B-aligned float
        int head = (int)(a0 - base_f);                  // 0..3
        if (tid < head) s_stage[tid] = __ldg(conf + base_f + tid);
        int rest = elems - head;
        int nq = rest >> 2;
        const float4* cq = (const float4*)conf + (a0 >> 2);
        for (int q = tid; q < nq; q += WT) {
            float4 v = __ldg(cq + q);
            int s = head + q*4;
            s_stage[s+0] = v.x; s_stage[s+1] = v.y;
            s_stage[s+2] = v.z; s_stage[s+3] = v.w;
        }
        int tstart = head + nq*4;
        if (tid < elems - tstart)                       // 0..3 tail scalars
            s_stage[tstart + tid] = __ldg(conf + base_f + tstart + tid);
        __syncthreads();
        if (tid < rows) {
            const float* r = s_stage + tid * C;         // stride 21: conflict-free
            float mx = r[0];
            #pragma unroll
            for (int c2 = 1; c2 < C; c2++) mx = fmaxf(mx, r[c2]);
            float s = 0.0f;
            #pragma unroll
            for (int c2 = 0; c2 < C; c2++) s += __expf(r[c2] - mx);
            float lse = mx + __logf(s);
            g_mine[(size_t)b*P + t0 + tid] = lse - r[0];
        }
    }
}

// ------------- kernel 2: fixup + hard-negative mining + final ------------------
#define HC         8                         // histogram copies
#define MOFF_V     0                         // P floats
#define MOFF_CODE  (MOFF_V + P*4)            // P bytes
#define MOFF_RED   ((MOFF_CODE + P + 15) & ~15)  // 1024 floats (final reduce)
#define MOFF_CNT   (MOFF_RED + 1024*4)       // 1056 ints
#define MOFF_HIST  (MOFF_CNT + 1056*4)       // HC*256 ints
#define MOFF_HC    (MOFF_HIST + HC*256*4)    // 256 ints combined
#define MOFF_TR    (MOFF_HC + 256*4)         // 100 floats
#define MOFF_P2    (MOFF_TR + 100*4)         // 20 ints
#define MOFF_W1    (MOFF_P2 + 20*4)          // 32 floats (warp stage A)
#define MOFF_W2    (MOFF_W1 + 32*4)          // 32 floats (warp stage B)
#define MOFF_SCAL  (MOFF_W2 + 32*4)          // scalars
#define MSMEM      (MOFF_SCAL + 32)

__global__ __launch_bounds__(1024) void k_minefix(const float*  __restrict__ conf,
                                                  const float4* __restrict__ priors,
                                                  const float*  __restrict__ loc,
                                                  const float*  __restrict__ targets,
                                                  float* __restrict__ out)
{
    extern __shared__ unsigned char msm[];
    float*         s_v    = (float*)(msm + MOFF_V);
    unsigned char* s_code = msm + MOFF_CODE;
    float*         s_red  = (float*)(msm + MOFF_RED);
    int*           cnts   = (int*)  (msm + MOFF_CNT);
    int*           hist   = (int*)  (msm + MOFF_HIST);
    int*           histC  = (int*)  (msm + MOFF_HC);
    float*         s_tr   = (float*)(msm + MOFF_TR);
    int*           s_p2   = (int*)  (msm + MOFF_P2);
    float*         s_w1   = (float*)(msm + MOFF_W1);
    float*         s_w2   = (float*)(msm + MOFF_W2);
    unsigned*      s_pref = (unsigned*)(msm + MOFF_SCAL);
    int*           s_klft = (int*)  (msm + MOFF_SCAL + 4);
    float*         s_ce0  = (float*)(msm + MOFF_SCAL + 8);
    int*           s_last = (int*)  (msm + MOFF_SCAL + 12);
    int*           s_npt  = (int*)  (msm + MOFF_SCAL + 16);
    int* s_ws = cnts + 1024;

    int b = blockIdx.x, tid = threadIdx.x;
    int lane = tid & 31, wid = tid >> 5;

    // load mining values (float4: P%4==0) and code bytes
    const float4* gm4 = (const float4*)(g_mine + (size_t)b*P);
    float4* sv4 = (float4*)s_v;
    for (int i = tid; i < P/4; i += 1024) sv4[i] = gm4[i];
    const unsigned* gc = (const unsigned*)(g_code + b*P);
    unsigned* sc = (unsigned*)s_code;
    for (int i = tid; i < P/4; i += 1024) sc[i] = gc[i];
    if (tid < NOBJ*5) s_tr[tid] = targets[b*NOBJ*5 + tid];
    if (tid < NOBJ) {
        ull k = 0ull;                          // reduce 2 per-half slots
        #pragma unroll
        for (int o = 0; o < S2; o++) {
            ull x = g_bp2[(b*S2 + o)*NOBJ + tid];
            if (x > k) k = x;
        }
        s_p2[tid] = (int)(0xFFFFFFFFu - (unsigned)(k & 0xFFFFFFFFull));
    }
    __syncthreads();
    if (tid == 0) {   // ascending m, last write wins = JAX "chosen = max n"
        for (int m = 0; m < NOBJ; m++) s_code[s_p2[m]] = (unsigned char)(m | 0x80);
    }
    __syncthreads();

    // ---- fixup: positives -> ce into accumulator, s_v[p] = -1; loc loss ------
    float ll = 0.0f, ce_pos = 0.0f; int np = 0;
    for (int p = tid; p < P; p += 1024) {
        unsigned char code = s_code[p];
        size_t idx = (size_t)b*P + p;
        if (code & 0x80) {
            int n = code & 31;
            np++;
            int cf = (int)s_tr[n*5+4] + 1;
            float r0  = __ldg(conf + idx*C);
            float rcf = __ldg(conf + idx*C + cf);
            ce_pos += s_v[p] + r0 - rcf;               // (lse-r0)+r0-rcf
            s_v[p] = -1.0f;
            float4 pr = __ldg(priors + p);
            float a0 = s_tr[n*5+0], a1 = s_tr[n*5+1];
            float a2 = s_tr[n*5+2], a3 = s_tr[n*5+3];
            float gx = ((a0 + a2) * 0.5f - pr.x) / (0.1f * pr.z);
            float gy = ((a1 + a3) * 0.5f - pr.y) / (0.1f * pr.w);
            float gw = logf((a2 - a0) / pr.z) * 5.0f;
            float gh = logf((a3 - a1) / pr.w) * 5.0f;
            float4 ld = __ldg(((const float4*)loc) + idx);
            ll += sl1(ld.x - gx) + sl1(ld.y - gy) + sl1(ld.z - gw) + sl1(ld.w - gh);
        } else if (b == 0 && p == 0) {
            // clamped[0]=1 quirk: recompute lse with IDENTICAL op sequence
            float rr[C];
            #pragma unroll
            for (int c2 = 0; c2 < C; c2++) rr[c2] = __ldg(conf + c2);
            float mx = rr[0];
            #pragma unroll
            for (int c2 = 1; c2 < C; c2++) mx = fmaxf(mx, rr[c2]);
            float s = 0.0f;
            #pragma unroll
            for (int c2 = 0; c2 < C; c2++) s += __expf(rr[c2] - mx);
            float lse = mx + __logf(s);
            *s_ce0 = lse - rr[0];                      // true CE if selected
            s_v[0] = lse - rr[1];                      // mining value uses class 1
        }
    }
    // ---- np reduce: warp shuffle + 32-slot stage (2 barriers) ----------------
    #pragma unroll
    for (int o = 16; o > 0; o >>= 1) np += __shfl_down_sync(0xffffffffu, np, o);
    if (lane == 0) s_ws[wid] = np;
    __syncthreads();
    if (wid == 0) {
        int v = s_ws[lane];
        #pragma unroll
        for (int o = 16; o > 0; o >>= 1) v += __shfl_down_sync(0xffffffffu, v, o);
        if (lane == 0) *s_npt = v;
    }
    __syncthreads();
    int np_tot = *s_npt;

    // ---- mining: exact top-k radix select, 8-way privatized histograms -------
    int k = 3 * np_tot; if (k > P - 1) k = P - 1;
    int negc = P - np_tot;
    const int CH = (P + 1023) / 1024;                  // 9
    int lo = tid * CH, hi = min(lo + CH, P);
    float nsum = 0.0f;
    int* myhist = hist + (wid & (HC-1)) * 256;

    if (k >= negc) {
        for (int i = lo; i < hi; i++) { float v = s_v[i]; if (v >= 0.0f) nsum += v; }
        if (b == 0 && tid == 0) { float v0 = s_v[0]; if (v0 >= 0.0f) nsum += *s_ce0 - v0; }
    } else {
        unsigned pref = 0; int kleft = k;
        for (int shift = 24; shift >= 0; shift -= 8) {
            for (int i = tid; i < HC*256; i += 1024) hist[i] = 0;
            __syncthreads();
            for (int i = lo; i < hi; i++) {
                float v = s_v[i];
                unsigned key = (v < 0.0f) ? 0u : __float_as_uint(v);
                unsigned kh = key >> shift;
                bool ok = (shift == 24) || ((kh >> 8) == pref);
                if (ok) atomicAdd(&myhist[kh & 255u], 1);
            }
            __syncthreads();
            if (tid < 256) {
                int s = 0;
                #pragma unroll
                for (int c2 = 0; c2 < HC; c2++) s += hist[c2*256 + tid];
                histC[tid] = s;
            }
            __syncthreads();
            if (wid == 0) {                            // warp-only bin select
                int c[8]; int tot = 0;
                #pragma unroll
                for (int j = 0; j < 8; j++) { c[j] = histC[lane*8 + j]; tot += c[j]; }
                int suf = tot;
                #pragma unroll
                for (int o = 1; o < 32; o <<= 1) {
                    int y = __shfl_down_sync(0xffffffffu, suf, o);
                    if (lane + o < 32) suf += y;
                }
                int cum = suf - tot;
                #pragma unroll
                for (int j = 7; j >= 0; j--) {
                    if (cum < kleft && cum + c[j] >= kleft) {
                        *s_pref = (pref << 8) | (unsigned)(lane*8 + j);
                        *s_klft = kleft - cum;
                    }
                    cum += c[j];
                }
            }
            __syncthreads();
            pref = *s_pref; kleft = *s_klft;
        }
        unsigned T = pref; int quota = kleft;          // quota >= 1

        int ct = 0;
        for (int i = lo; i < hi; i++) {
            float v = s_v[i];
            unsigned key = (v < 0.0f) ? 0u : __float_as_uint(v);
            if (key > T) nsum += v;
            else if (key == T && v >= 0.0f) ct++;
        }
        int cin = ct;
        #pragma unroll
        for (int o = 1; o < 32; o <<= 1) {
            int n2 = __shfl_up_sync(0xffffffffu, cin, o);
            if (lane >= o) cin += n2;
        }
        if (lane == 31) s_ws[wid] = cin;
        __syncthreads();
        if (wid == 0) {
            int w = s_ws[lane];
            #pragma unroll
            for (int o = 1; o < 32; o <<= 1) {
                int n2 = __shfl_up_sync(0xffffffffu, w, o);
                if (lane >= o) w += n2;
            }
            s_ws[lane] = w;
        }
        __syncthreads();
        int off0 = ((wid == 0) ? 0 : s_ws[wid - 1]) + (cin - ct);
        int r2 = 0;
        for (int i = lo; i < hi; i++) {                // ties stable by index
            float v = s_v[i];
            unsigned key = (v < 0.0f) ? 0u : __float_as_uint(v);
            if (key == T && v >= 0.0f) {
                if (off0 + r2 < quota) nsum += v;
                r2++;
            }
        }
        if (b == 0 && tid == 0) {
            float v0 = s_v[0];
            if (v0 >= 0.0f && __float_as_uint(v0) >= T) nsum += *s_ce0 - v0;
        }
    }

    // ---- ll & lc reduce: warp shuffle + 32-slot stages (2 barriers total) ----
    float lc = ce_pos + nsum;
    #pragma unroll
    for (int o = 16; o > 0; o >>= 1) {
        lc += __shfl_down_sync(0xffffffffu, lc, o);
        ll += __shfl_down_sync(0xffffffffu, ll, o);
    }
    if (lane == 0) { s_w1[wid] = lc; s_w2[wid] = ll; }
    __syncthreads();
    if (wid == 0) {
        float a = s_w1[lane], d = s_w2[lane];
        #pragma unroll
        for (int o = 16; o > 0; o >>= 1) {
            a += __shfl_down_sync(0xffffffffu, a, o);
            d += __shfl_down_sync(0xffffffffu, d, o);
        }
        if (lane == 0) {
            g_ll[b] = d; g_lc[b] = a; g_np[b] = np_tot;
            __threadfence();
            unsigned t = atomicAdd(&g_ticket, 1u);
            *s_last = ((t % B) == B - 1);              // phase-correct, no reset
        }
    }
    __syncthreads();

    if (*s_last) {                                     // last block: final reduce
        __threadfence();
        float llg = 0.0f, lcg = 0.0f; int npg = 0;
        if (tid < B) { llg = g_ll[tid]; lcg = g_lc[tid]; npg = g_np[tid]; }
        s_red[tid] = llg; s_v[tid] = lcg; cnts[tid] = npg;
        __syncthreads();
        for (int o = 64; o > 0; o >>= 1) {
            if (tid < o) { s_red[tid] += s_red[tid+o]; s_v[tid] += s_v[tid+o]; cnts[tid] += cnts[tid+o]; }
            __syncthreads();
        }
        if (tid == 0) {
            float Nf = (float)cnts[0];
            out[0] = s_red[0] / Nf;
            out[1] = s_v[0] / Nf;
        }
    }
}

// ------------- launch ------------------------------------------------------------
extern "C" void kernel_launch(void* const* d_in, const int* in_sizes, int n_in,
                              void* d_out, int out_size)
{
    const float *loc = nullptr, *conf = nullptr, *priors = nullptr, *targets = nullptr;
    for (int i = 0; i < n_in; i++) {
        long long sz = in_sizes[i];
        if      (sz == (long long)B*P*4)     loc     = (const float*)d_in[i];
        else if (sz == (long long)B*P*C)     conf    = (const float*)d_in[i];
        else if (sz == (long long)P*4)       priors  = (const float*)d_in[i];
        else if (sz == (long long)B*NOBJ*5)  targets = (const float*)d_in[i];
    }
    static int attr_done = 0;
    if (!attr_done) {
        cudaFuncSetAttribute(k_minefix, cudaFuncAttributeMaxDynamicSharedMemorySize, MSMEM);
        attr_done = 1;
    }
    k_work   <<<NWORK, WT, LBYTES>>>(conf, (const float4*)priors, targets);
    k_minefix<<<B, 1024, MSMEM>>>(conf, (const float4*)priors, loc, targets, (float*)d_out);
    (void)out_size;
}